// round 1
// baseline (speedup 1.0000x reference)
#include <cuda_runtime.h>
#include <math_constants.h>

#define N_SEG 128
#define P     512
#define D     64
#define KT    15
#define NC    8

__device__ float g_partials[N_SEG];

__global__ __launch_bounds__(512, 1)
void lmnn_seg_kernel(const float* __restrict__ center,
                     const float* __restrict__ outputs,
                     const int*   __restrict__ labels)
{
    __shared__ float sdist[P];
    __shared__ int   slab[P];
    __shared__ float sS[NC];
    __shared__ float sM[NC];
    __shared__ int   sCnt[NC];
    __shared__ float sred[16];

    const int i = blockIdx.x;
    const int t = threadIdx.x;
    const int w = t >> 5;
    const int lane = t & 31;

    // ---- load labels (one per thread) ----
    slab[t] = labels[i * P + t];

    // ---- Phase 1: dist_c[j] = ||outputs[i,j,:] - center[i,:]||^2 ----
    // Flattened as 8192 float4s; thread t handles g = t + 512*s.
    // (t & 15) determines the d-offset of the float4 (constant across s),
    // so each thread needs exactly one float4 of the center.
    const float4* __restrict__ out4 = (const float4*)(outputs + (size_t)i * P * D);
    const float4  c4 = ((const float4*)(center + i * D))[t & 15];

    #pragma unroll
    for (int s = 0; s < 16; ++s) {
        const int g = t + 512 * s;
        float4 v = out4[g];
        float dx = v.x - c4.x;
        float dy = v.y - c4.y;
        float dz = v.z - c4.z;
        float dw = v.w - c4.w;
        float part = dx * dx + dy * dy + dz * dz + dw * dw;
        // reduce groups of 16 lanes (one point = 16 consecutive float4s)
        part += __shfl_down_sync(0xffffffffu, part, 8);
        part += __shfl_down_sync(0xffffffffu, part, 4);
        part += __shfl_down_sync(0xffffffffu, part, 2);
        part += __shfl_down_sync(0xffffffffu, part, 1);
        if ((t & 15) == 0) sdist[g >> 4] = part;
    }
    __syncthreads();

    // ---- Phase 2: per-class stats. Warp w (< 8) handles class c = w. ----
    // Key simplification: top_k over -dd has all finite entries equal
    // (dist_c[j] broadcast), so jax tie-breaking selects the FIRST 15
    // same-class indices. We take the first KT members in index order.
    if (w < NC) {
        const int c = w;
        float S  = 0.0f;
        float Mx = -CUDART_INF_F;
        int   cnt = 0;
        int   taken = 0;
        #pragma unroll 4
        for (int base = 0; base < P; base += 32) {
            const bool m = (slab[base + lane] == c);
            const unsigned mask = __ballot_sync(0xffffffffu, m);
            const int pc = __popc(mask);
            const int need = KT - taken;
            if (need > 0) {
                const int rank = __popc(mask & ((1u << lane) - 1u));
                if (m && rank < need) {
                    const float dv = sdist[base + lane];
                    S += dv;
                    Mx = fmaxf(Mx, dv);
                }
                taken += (pc < need) ? pc : need;
            }
            cnt += pc;
        }
        #pragma unroll
        for (int off = 16; off > 0; off >>= 1) {
            S += __shfl_xor_sync(0xffffffffu, S, off);
            Mx = fmaxf(Mx, __shfl_xor_sync(0xffffffffu, Mx, off));
        }
        if (lane == 0) { sS[c] = S; sM[c] = Mx; sCnt[c] = cnt; }
    }
    __syncthreads();

    // ---- Phase 3: margin_seg = 1 + max over present classes of M_c ----
    float ms = -CUDART_INF_F;
    #pragma unroll
    for (int c = 0; c < NC; ++c)
        if (sCnt[c] > 0) ms = fmaxf(ms, sM[c]);
    ms += 1.0f;

    // ---- Phase 4: push term per point j = t ----
    const int   cj = slab[t];
    const float dv = sdist[t];
    float term = 0.0f;
    if (dv < ms) {
        term = (float)(P - sCnt[cj]) * fmaxf(1.0f + sM[cj] - dv, 0.0f);
    }
    // block reduce over 512 threads
    #pragma unroll
    for (int off = 16; off > 0; off >>= 1)
        term += __shfl_xor_sync(0xffffffffu, term, off);
    if (lane == 0) sred[w] = term;
    __syncthreads();

    if (w == 0) {
        float v = (lane < 16) ? sred[lane] : 0.0f;
        #pragma unroll
        for (int off = 8; off > 0; off >>= 1)
            v += __shfl_xor_sync(0xffffffffu, v, off);
        if (lane == 0) {
            // pull = sum_c cnt_c * S_c (S_c = 0 when cnt_c = 0)
            float pull = 0.0f;
            #pragma unroll
            for (int c = 0; c < NC; ++c)
                pull += (float)sCnt[c] * sS[c];
            g_partials[i] = pull + v;
        }
    }
}

__global__ void lmnn_final_kernel(float* __restrict__ out)
{
    __shared__ float s[4];
    const int t = threadIdx.x;
    float v = g_partials[t];
    #pragma unroll
    for (int off = 16; off > 0; off >>= 1)
        v += __shfl_xor_sync(0xffffffffu, v, off);
    if ((t & 31) == 0) s[t >> 5] = v;
    __syncthreads();
    if (t == 0)
        out[0] = (s[0] + s[1] + s[2] + s[3]) * (1.0f / (float)(N_SEG * P));
}

extern "C" void kernel_launch(void* const* d_in, const int* in_sizes, int n_in,
                              void* d_out, int out_size)
{
    const float* center  = (const float*)d_in[0];  // (128, 64)   f32
    const float* outputs = (const float*)d_in[1];  // (128,512,64) f32
    const int*   labels  = (const int*)d_in[2];    // (128, 512)  i32

    lmnn_seg_kernel<<<N_SEG, 512>>>(center, outputs, labels);
    lmnn_final_kernel<<<1, N_SEG>>>((float*)d_out);
}